// round 8
// baseline (speedup 1.0000x reference)
#include <cuda_runtime.h>

// Problem constants (fixed by reference)
#define NN 50000
#define EE 500000
#define FD 128
#define RR 8
#define NF (NN * FD)            // 6,400,000 floats
#define XWSZ (RR * NN * FD)     // 51,200,000 floats (~205 MB)

// Scratch (device globals: allocation-free per harness rules)
__device__ float g_xw[XWSZ];    // [r][n][g] transformed features per relation
__device__ float g_h1[NF];      // layer-1 output (input to layer 2)
__device__ float g_acc[NF];     // aggregation accumulator
__device__ float g_sq[NN * RR]; // s_q[n][r] = h[n] . (W[r] q)
__device__ float g_sk[NN * RR]; // s_k[n][r] = h[n] . (W[r] k)
__device__ float g_wq[RR * FD];
__device__ float g_wk[RR * FD];
__device__ float g_e[EE];       // logits, then exp values (in place)
__device__ float g_maxv[NN];    // segment max per dst
__device__ float g_den[NN];     // segment sum per dst

// ---------------------------------------------------------------------------
// Init: zero acc, set maxv=-inf, den=0
// ---------------------------------------------------------------------------
__global__ void k_init() {
    int i = blockIdx.x * blockDim.x + threadIdx.x;
    if (i < NF) g_acc[i] = 0.0f;
    if (i < NN) {
        g_maxv[i] = __int_as_float(0xff800000);  // -inf
        g_den[i] = 0.0f;
    }
}

// ---------------------------------------------------------------------------
// wq[r][f] = sum_g W[l][r][f][g] * q[g];  wk likewise with k.
// One thread per (r,f) = 1024 threads.
// ---------------------------------------------------------------------------
__global__ void k_wqk(const float* __restrict__ W,
                      const float* __restrict__ aq,
                      const float* __restrict__ ak, int layer) {
    int i = blockIdx.x * blockDim.x + threadIdx.x;  // i = r*FD + f
    if (i >= RR * FD) return;
    const float* wrow = W + (size_t)layer * RR * FD * FD + (size_t)i * FD;
    const float* q = aq + (size_t)layer * FD;
    const float* k = ak + (size_t)layer * FD;
    float sq = 0.0f, sk = 0.0f;
    #pragma unroll 8
    for (int g = 0; g < FD; g++) {
        float w = wrow[g];
        sq += w * q[g];
        sk += w * k[g];
    }
    g_wq[i] = sq;
    g_wk[i] = sk;
}

// ---------------------------------------------------------------------------
// GEMM: xw[r][n][g] = sum_f h[n][f] * W[l][r][f][g]
// Tile 128(m) x 128(n) x 8(k), 256 threads, 8x8 register micro-tiles.
// blockIdx.z = relation r.
// ---------------------------------------------------------------------------
__global__ __launch_bounds__(256) void k_gemm(const float* __restrict__ x,
                                              const float* __restrict__ W,
                                              int layer) {
    __shared__ float As[8][128];  // [k][m]
    __shared__ float Bs[8][128];  // [k][n]

    const float* A = layer ? g_h1 : x;
    int r = blockIdx.z;
    const float* B = W + ((size_t)layer * RR + r) * FD * FD;

    int m0 = blockIdx.x * 128;
    int t = threadIdx.x;
    int tr = (t >> 4) * 8;       // 0..120 (row offset of micro-tile)
    int tc = (t & 15) * 8;       // 0..120 (col offset of micro-tile)

    // load assignments
    int la_m = t >> 1;           // 0..127
    int la_k = (t & 1) * 4;      // 0 or 4
    int lb_k = t >> 5;           // 0..7
    int lb_n = (t & 31) * 4;     // 0..124

    float acc[8][8];
    #pragma unroll
    for (int i = 0; i < 8; i++)
        #pragma unroll
        for (int j = 0; j < 8; j++) acc[i][j] = 0.0f;

    for (int k0 = 0; k0 < FD; k0 += 8) {
        int arow = m0 + la_m;
        if (arow >= NN) arow = NN - 1;  // clamp (stores are guarded)
        float4 av = *(const float4*)(A + (size_t)arow * FD + k0 + la_k);
        As[la_k + 0][la_m] = av.x;
        As[la_k + 1][la_m] = av.y;
        As[la_k + 2][la_m] = av.z;
        As[la_k + 3][la_m] = av.w;
        float4 bv = *(const float4*)(B + (size_t)(k0 + lb_k) * FD + lb_n);
        *(float4*)(&Bs[lb_k][lb_n]) = bv;
        __syncthreads();

        #pragma unroll
        for (int kk = 0; kk < 8; kk++) {
            float a[8], b[8];
            *(float4*)(a)     = *(const float4*)(&As[kk][tr]);
            *(float4*)(a + 4) = *(const float4*)(&As[kk][tr + 4]);
            *(float4*)(b)     = *(const float4*)(&Bs[kk][tc]);
            *(float4*)(b + 4) = *(const float4*)(&Bs[kk][tc + 4]);
            #pragma unroll
            for (int i = 0; i < 8; i++)
                #pragma unroll
                for (int j = 0; j < 8; j++) acc[i][j] += a[i] * b[j];
        }
        __syncthreads();
    }

    #pragma unroll
    for (int i = 0; i < 8; i++) {
        int row = m0 + tr + i;
        if (row < NN) {
            float* dst = g_xw + ((size_t)r * NN + row) * FD + tc;
            *(float4*)(dst)     = make_float4(acc[i][0], acc[i][1], acc[i][2], acc[i][3]);
            *(float4*)(dst + 4) = make_float4(acc[i][4], acc[i][5], acc[i][6], acc[i][7]);
        }
    }
}

// ---------------------------------------------------------------------------
// Per-node attention scores: s_q[n][r] = h[n].wq[r], s_k[n][r] = h[n].wk[r]
// One warp per node.
// ---------------------------------------------------------------------------
__global__ void k_s(const float* __restrict__ x, int layer) {
    __shared__ float swq[RR * FD];
    __shared__ float swk[RR * FD];
    for (int i = threadIdx.x; i < RR * FD; i += blockDim.x) {
        swq[i] = g_wq[i];
        swk[i] = g_wk[i];
    }
    __syncthreads();

    const float* h = layer ? g_h1 : x;
    int gwarp = (blockIdx.x * blockDim.x + threadIdx.x) >> 5;
    int lane = threadIdx.x & 31;
    if (gwarp >= NN) return;

    float4 v = *(const float4*)(h + (size_t)gwarp * FD + lane * 4);
    #pragma unroll
    for (int r = 0; r < RR; r++) {
        const float* wr = swq + r * FD + lane * 4;
        float p = v.x * wr[0] + v.y * wr[1] + v.z * wr[2] + v.w * wr[3];
        #pragma unroll
        for (int o = 16; o; o >>= 1) p += __shfl_xor_sync(0xffffffffu, p, o);
        if (lane == 0) g_sq[gwarp * RR + r] = p;

        const float* wr2 = swk + r * FD + lane * 4;
        float p2 = v.x * wr2[0] + v.y * wr2[1] + v.z * wr2[2] + v.w * wr2[3];
        #pragma unroll
        for (int o = 16; o; o >>= 1) p2 += __shfl_xor_sync(0xffffffffu, p2, o);
        if (lane == 0) g_sk[gwarp * RR + r] = p2;
    }
}

// ---------------------------------------------------------------------------
// Pass A: logits + segment max (float atomic max via signed-max / unsigned-min)
// ---------------------------------------------------------------------------
__global__ void k_logit(const int* __restrict__ ei, const int* __restrict__ et) {
    int e = blockIdx.x * blockDim.x + threadIdx.x;
    if (e >= EE) return;
    int s = ei[e];
    int d = ei[EE + e];
    int r = et[e];
    float xsum = g_sq[d * RR + r] + g_sk[s * RR + r];
    float lg = xsum > 0.0f ? xsum : 0.2f * xsum;  // leaky_relu, slope 0.2
    g_e[e] = lg;
    if (lg >= 0.0f)
        atomicMax((int*)(g_maxv + d), __float_as_int(lg));
    else
        atomicMin((unsigned int*)(g_maxv + d), __float_as_uint(lg));
}

// ---------------------------------------------------------------------------
// Pass B: exp(logit - max), segment sum
// ---------------------------------------------------------------------------
__global__ void k_expden(const int* __restrict__ ei) {
    int e = blockIdx.x * blockDim.x + threadIdx.x;
    if (e >= EE) return;
    int d = ei[EE + e];
    float v = expf(g_e[e] - g_maxv[d]);
    g_e[e] = v;
    atomicAdd(g_den + d, v);
}

// ---------------------------------------------------------------------------
// Pass C: acc[d] += (e/denom) * xw[et][src]   (one warp per edge)
// ---------------------------------------------------------------------------
__global__ void k_agg(const int* __restrict__ ei, const int* __restrict__ et) {
    int g = blockIdx.x * blockDim.x + threadIdx.x;
    int e = g >> 5;
    int lane = g & 31;
    if (e >= EE) return;
    int s = ei[e];
    int d = ei[EE + e];
    int r = et[e];
    float coef = g_e[e] / (g_den[d] + 1e-16f);
    float4 v = *(const float4*)(g_xw + ((size_t)r * NN + s) * FD + lane * 4);
    float* a = g_acc + (size_t)d * FD + lane * 4;
    atomicAdd(a + 0, coef * v.x);
    atomicAdd(a + 1, coef * v.y);
    atomicAdd(a + 2, coef * v.z);
    atomicAdd(a + 3, coef * v.w);
}

// ---------------------------------------------------------------------------
// Epilogue: out = relu(acc + bias)
// ---------------------------------------------------------------------------
__global__ void k_out(const float* __restrict__ bias, float* __restrict__ out,
                      int layer) {
    int i = blockIdx.x * blockDim.x + threadIdx.x;
    if (i >= NF) return;
    float v = g_acc[i] + bias[(size_t)layer * FD + (i & (FD - 1))];
    v = v > 0.0f ? v : 0.0f;
    if (layer)
        out[i] = v;
    else
        g_h1[i] = v;
}

// ---------------------------------------------------------------------------
extern "C" void kernel_launch(void* const* d_in, const int* in_sizes, int n_in,
                              void* d_out, int out_size) {
    const float* x    = (const float*)d_in[0];  // [N, F]
    const float* W    = (const float*)d_in[1];  // [L, R, F, F]
    const float* aq   = (const float*)d_in[2];  // [L, F, 1]
    const float* ak   = (const float*)d_in[3];  // [L, F, 1]
    const float* bias = (const float*)d_in[4];  // [L, F]
    const int*   ei   = (const int*)d_in[5];    // [2, E]
    const int*   et   = (const int*)d_in[6];    // [E]
    float* out = (float*)d_out;                 // [N, F]

    for (int l = 0; l < 2; l++) {
        k_init<<<(NF + 255) / 256, 256>>>();
        k_wqk<<<(RR * FD + 255) / 256, 256>>>(W, aq, ak, l);
        dim3 gg((NN + 127) / 128, 1, RR);
        k_gemm<<<gg, 256>>>(x, W, l);
        k_s<<<(NN * 32 + 255) / 256, 256>>>(x, l);
        k_logit<<<(EE + 255) / 256, 256>>>(ei, et);
        k_expden<<<(EE + 255) / 256, 256>>>(ei);
        k_agg<<<(EE * 32 + 255) / 256, 256>>>(ei, et);
        k_out<<<(NF + 255) / 256, 256>>>(bias, out, l);
    }
}

// round 15
// speedup vs baseline: 1.4275x; 1.4275x over previous
#include <cuda_runtime.h>
#include <cuda_bf16.h>
#include <cstdint>

// Problem constants
#define NN 50000
#define EE 500000
#define FD 128
#define RR 8
#define NF (NN * FD)
#define XWSZ (RR * NN * FD)
#define WSZ (RR * FD * FD)

// Scratch (device globals; allocation-free)
__device__ float g_xw[XWSZ];          // [r][n][g]
__device__ float g_h1[NF];
__device__ float g_acc[NF];
__device__ float g_sq[NN * RR];
__device__ float g_sk[NN * RR];
__device__ float g_wq[RR * FD];
__device__ float g_wk[RR * FD];
__device__ float g_e[EE];
__device__ float g_maxv[NN];
__device__ float g_den[NN];
__device__ __nv_bfloat16 g_hh[NF];    // h hi (bf16)
__device__ __nv_bfloat16 g_hl[NF];    // h lo (bf16 residual)
__device__ __nv_bfloat16 g_wth[WSZ];  // W^T hi  [r][g][f]
__device__ __nv_bfloat16 g_wtl[WSZ];  // W^T lo

// ---------------------------------------------------------------------------
__device__ __forceinline__ uint32_t smem_u32(const void* p) {
    uint32_t a;
    asm("{ .reg .u64 t; cvta.to.shared.u64 t, %1; cvt.u32.u64 %0, t; }"
        : "=r"(a) : "l"(p));
    return a;
}

// ---------------------------------------------------------------------------
__global__ void k_init() {
    int i = blockIdx.x * blockDim.x + threadIdx.x;
    if (i < NF) g_acc[i] = 0.0f;
    if (i < NN) {
        g_maxv[i] = __int_as_float(0xff800000);
        g_den[i] = 0.0f;
    }
}

// h (f32) -> bf16 hi/lo, 4 elems/thread
__global__ void k_conv_h(const float* __restrict__ x, int layer) {
    int i = blockIdx.x * blockDim.x + threadIdx.x;
    if (i >= NF / 4) return;
    const float* src = layer ? g_h1 : x;
    float4 v = ((const float4*)src)[i];
    __nv_bfloat16 hx = __float2bfloat16(v.x), hy = __float2bfloat16(v.y);
    __nv_bfloat16 hz = __float2bfloat16(v.z), hw = __float2bfloat16(v.w);
    __nv_bfloat162 p0 = __halves2bfloat162(hx, hy);
    __nv_bfloat162 p1 = __halves2bfloat162(hz, hw);
    uint2 hi; hi.x = *(uint32_t*)&p0; hi.y = *(uint32_t*)&p1;
    ((uint2*)g_hh)[i] = hi;
    __nv_bfloat162 l0 = __halves2bfloat162(
        __float2bfloat16(v.x - __bfloat162float(hx)),
        __float2bfloat16(v.y - __bfloat162float(hy)));
    __nv_bfloat162 l1 = __halves2bfloat162(
        __float2bfloat16(v.z - __bfloat162float(hz)),
        __float2bfloat16(v.w - __bfloat162float(hw)));
    uint2 lo; lo.x = *(uint32_t*)&l0; lo.y = *(uint32_t*)&l1;
    ((uint2*)g_hl)[i] = lo;
}

// W[l][r][f][g] (f32) -> transposed bf16 hi/lo [r][g][f]
__global__ void k_conv_w(const float* __restrict__ W, int layer) {
    int idx = blockIdx.x * blockDim.x + threadIdx.x;
    if (idx >= WSZ) return;
    int f = idx & 127, g = (idx >> 7) & 127, r = idx >> 14;
    float v = W[(size_t)layer * WSZ + ((size_t)r * FD + f) * FD + g];
    __nv_bfloat16 h = __float2bfloat16(v);
    g_wth[idx] = h;
    g_wtl[idx] = __float2bfloat16(v - __bfloat162float(h));
}

// wq[r][f] = sum_g W[l][r][f][g] * q[g];  wk likewise.
__global__ void k_wqk(const float* __restrict__ W,
                      const float* __restrict__ aq,
                      const float* __restrict__ ak, int layer) {
    int i = blockIdx.x * blockDim.x + threadIdx.x;
    if (i >= RR * FD) return;
    const float* wrow = W + (size_t)layer * RR * FD * FD + (size_t)i * FD;
    const float* q = aq + (size_t)layer * FD;
    const float* k = ak + (size_t)layer * FD;
    float sq = 0.0f, sk = 0.0f;
    #pragma unroll 8
    for (int g = 0; g < FD; g++) {
        float w = wrow[g];
        sq += w * q[g];
        sk += w * k[g];
    }
    g_wq[i] = sq;
    g_wk[i] = sk;
}

// ---------------------------------------------------------------------------
// Tensor-core GEMM via mma.sync (HMMA, arch-neutral PTX, compiles on sm_103):
// xw[r][m][g] = sum_f h[m][f] W[f][g], bf16 hi/lo split (3 passes).
// CTA tile 128x128, K=128 fully resident. 8 warps: 4(m) x 2(n), 32x64 each.
// ---------------------------------------------------------------------------
#define PADK 136                      // row stride in bf16 (272B: LDSM conflict-free)
#define TILEB (128 * PADK * 2)        // 34816 B per tile
#define GSMEM (4 * TILEB)             // Ah, Al, Bh, Bl

__device__ __forceinline__ void ldsm4(uint32_t* d, uint32_t addr) {
    asm volatile("ldmatrix.sync.aligned.m8n8.x4.shared.b16 {%0,%1,%2,%3}, [%4];"
                 : "=r"(d[0]), "=r"(d[1]), "=r"(d[2]), "=r"(d[3]) : "r"(addr));
}
__device__ __forceinline__ void mma16816(float* c, const uint32_t* a,
                                         uint32_t b0, uint32_t b1) {
    asm volatile(
        "mma.sync.aligned.m16n8k16.row.col.f32.bf16.bf16.f32 "
        "{%0,%1,%2,%3}, {%4,%5,%6,%7}, {%8,%9}, {%0,%1,%2,%3};"
        : "+f"(c[0]), "+f"(c[1]), "+f"(c[2]), "+f"(c[3])
        : "r"(a[0]), "r"(a[1]), "r"(a[2]), "r"(a[3]), "r"(b0), "r"(b1));
}

__global__ __launch_bounds__(256) void k_gemm_mma(int unused) {
    extern __shared__ __nv_bfloat16 sm[];
    __nv_bfloat16* Ah = sm;
    __nv_bfloat16* Al = Ah + 128 * PADK;
    __nv_bfloat16* Bh = Al + 128 * PADK;
    __nv_bfloat16* Bl = Bh + 128 * PADK;

    int t = threadIdx.x;
    int m0 = blockIdx.x * 128, r = blockIdx.y;

    // ---- Global -> smem (8 bf16 per thread-iter, coalesced) ----
    const __nv_bfloat16* bsh = g_wth + (size_t)r * FD * FD;
    const __nv_bfloat16* bsl = g_wtl + (size_t)r * FD * FD;
    #pragma unroll
    for (int it = 0; it < 8; it++) {
        int item = t + it * 256;          // 0..2047
        int row = item >> 4, c8 = item & 15;
        int so = row * PADK + c8 * 8;
        int arow = m0 + row; if (arow >= NN) arow = NN - 1;
        *(uint4*)(Ah + so) = *(const uint4*)(g_hh + (size_t)arow * FD + c8 * 8);
        *(uint4*)(Al + so) = *(const uint4*)(g_hl + (size_t)arow * FD + c8 * 8);
        *(uint4*)(Bh + so) = *(const uint4*)(bsh + (size_t)row * FD + c8 * 8);
        *(uint4*)(Bl + so) = *(const uint4*)(bsl + (size_t)row * FD + c8 * 8);
    }
    __syncthreads();

    int wid = t >> 5, lane = t & 31;
    int wm = (wid & 3) * 32;              // warp m offset
    int wn = (wid >> 2) * 64;             // warp n offset
    int grp = lane >> 3, lr = lane & 7;

    uint32_t sbase = smem_u32(sm);
    // A lane address: row += (grp&1)*8 + lr ; col += (grp>>1)*8
    uint32_t a_l = (uint32_t)(((wm + (grp & 1) * 8 + lr) * PADK + (grp >> 1) * 8) * 2);
    // B lane address: row += (grp>>1)*8 + lr ; col += (grp&1)*8
    uint32_t b_l = (uint32_t)(((wn + (grp >> 1) * 8 + lr) * PADK + (grp & 1) * 8) * 2);

    float acc[2][8][4];
    #pragma unroll
    for (int i = 0; i < 2; i++)
        #pragma unroll
        for (int j = 0; j < 8; j++)
            #pragma unroll
            for (int q = 0; q < 4; q++) acc[i][j][q] = 0.0f;

    const uint32_t aoffs[3] = {0u, 0u, (uint32_t)TILEB};                 // Ah Ah Al
    const uint32_t boffs[3] = {2u * TILEB, 3u * TILEB, 2u * TILEB};      // Bh Bl Bh

    #pragma unroll
    for (int p = 0; p < 3; p++) {
        uint32_t abase = sbase + aoffs[p] + a_l;
        uint32_t bbase = sbase + boffs[p] + b_l;
        #pragma unroll
        for (int ks = 0; ks < 8; ks++) {
            uint32_t ak = abase + ks * 32;   // 16 bf16 = 32 B per k-step
            uint32_t bk = bbase + ks * 32;
            uint32_t afr[2][4], bfr[4][4];
            ldsm4(afr[0], ak);
            ldsm4(afr[1], ak + 16 * PADK * 2);
            #pragma unroll
            for (int nj = 0; nj < 4; nj++) ldsm4(bfr[nj], bk + nj * 16 * PADK * 2);
            #pragma unroll
            for (int mi = 0; mi < 2; mi++)
                #pragma unroll
                for (int nj = 0; nj < 8; nj++)
                    mma16816(acc[mi][nj], afr[mi],
                             bfr[nj >> 1][(nj & 1) * 2], bfr[nj >> 1][(nj & 1) * 2 + 1]);
        }
    }

    // ---- Epilogue: frag -> g_xw ----
    int qr = lane >> 2, c2 = (lane & 3) * 2;
    #pragma unroll
    for (int mi = 0; mi < 2; mi++) {
        int row0 = m0 + wm + mi * 16 + qr;
        #pragma unroll
        for (int nj = 0; nj < 8; nj++) {
            int col = wn + nj * 8 + c2;
            if (row0 < NN)
                *(float2*)(g_xw + ((size_t)r * NN + row0) * FD + col) =
                    make_float2(acc[mi][nj][0], acc[mi][nj][1]);
            if (row0 + 8 < NN)
                *(float2*)(g_xw + ((size_t)r * NN + row0 + 8) * FD + col) =
                    make_float2(acc[mi][nj][2], acc[mi][nj][3]);
        }
    }
}

// ---------------------------------------------------------------------------
// Per-node attention scores: one warp per node.
// ---------------------------------------------------------------------------
__global__ void k_s(const float* __restrict__ x, int layer) {
    __shared__ float swq[RR * FD];
    __shared__ float swk[RR * FD];
    for (int i = threadIdx.x; i < RR * FD; i += blockDim.x) {
        swq[i] = g_wq[i];
        swk[i] = g_wk[i];
    }
    __syncthreads();

    const float* h = layer ? g_h1 : x;
    int gwarp = (blockIdx.x * blockDim.x + threadIdx.x) >> 5;
    int lane = threadIdx.x & 31;
    if (gwarp >= NN) return;

    float4 v = *(const float4*)(h + (size_t)gwarp * FD + lane * 4);
    #pragma unroll
    for (int r = 0; r < RR; r++) {
        const float* wr = swq + r * FD + lane * 4;
        float p = v.x * wr[0] + v.y * wr[1] + v.z * wr[2] + v.w * wr[3];
        #pragma unroll
        for (int o = 16; o; o >>= 1) p += __shfl_xor_sync(0xffffffffu, p, o);
        if (lane == 0) g_sq[gwarp * RR + r] = p;

        const float* wr2 = swk + r * FD + lane * 4;
        float p2 = v.x * wr2[0] + v.y * wr2[1] + v.z * wr2[2] + v.w * wr2[3];
        #pragma unroll
        for (int o = 16; o; o >>= 1) p2 += __shfl_xor_sync(0xffffffffu, p2, o);
        if (lane == 0) g_sk[gwarp * RR + r] = p2;
    }
}

// ---------------------------------------------------------------------------
__global__ void k_logit(const int* __restrict__ ei, const int* __restrict__ et) {
    int e = blockIdx.x * blockDim.x + threadIdx.x;
    if (e >= EE) return;
    int s = ei[e];
    int d = ei[EE + e];
    int r = et[e];
    float xsum = g_sq[d * RR + r] + g_sk[s * RR + r];
    float lg = xsum > 0.0f ? xsum : 0.2f * xsum;
    g_e[e] = lg;
    if (lg >= 0.0f)
        atomicMax((int*)(g_maxv + d), __float_as_int(lg));
    else
        atomicMin((unsigned int*)(g_maxv + d), __float_as_uint(lg));
}

__global__ void k_expden(const int* __restrict__ ei) {
    int e = blockIdx.x * blockDim.x + threadIdx.x;
    if (e >= EE) return;
    int d = ei[EE + e];
    float v = expf(g_e[e] - g_maxv[d]);
    g_e[e] = v;
    atomicAdd(g_den + d, v);
}

__global__ void k_agg(const int* __restrict__ ei, const int* __restrict__ et) {
    int g = blockIdx.x * blockDim.x + threadIdx.x;
    int e = g >> 5;
    int lane = g & 31;
    if (e >= EE) return;
    int s = ei[e];
    int d = ei[EE + e];
    int r = et[e];
    float coef = g_e[e] / (g_den[d] + 1e-16f);
    float4 v = *(const float4*)(g_xw + ((size_t)r * NN + s) * FD + lane * 4);
    float* a = g_acc + (size_t)d * FD + lane * 4;
    atomicAdd(a + 0, coef * v.x);
    atomicAdd(a + 1, coef * v.y);
    atomicAdd(a + 2, coef * v.z);
    atomicAdd(a + 3, coef * v.w);
}

__global__ void k_out(const float* __restrict__ bias, float* __restrict__ out,
                      int layer) {
    int i = blockIdx.x * blockDim.x + threadIdx.x;
    if (i >= NF) return;
    float v = g_acc[i] + bias[(size_t)layer * FD + (i & (FD - 1))];
    v = v > 0.0f ? v : 0.0f;
    if (layer)
        out[i] = v;
    else
        g_h1[i] = v;
}

// ---------------------------------------------------------------------------
extern "C" void kernel_launch(void* const* d_in, const int* in_sizes, int n_in,
                              void* d_out, int out_size) {
    const float* x    = (const float*)d_in[0];
    const float* W    = (const float*)d_in[1];
    const float* aq   = (const float*)d_in[2];
    const float* ak   = (const float*)d_in[3];
    const float* bias = (const float*)d_in[4];
    const int*   ei   = (const int*)d_in[5];
    const int*   et   = (const int*)d_in[6];
    float* out = (float*)d_out;

    cudaFuncSetAttribute(k_gemm_mma,
                         cudaFuncAttributeMaxDynamicSharedMemorySize, GSMEM);

    for (int l = 0; l < 2; l++) {
        k_init<<<(NF + 255) / 256, 256>>>();
        k_conv_h<<<(NF / 4 + 255) / 256, 256>>>(x, l);
        k_conv_w<<<(WSZ + 255) / 256, 256>>>(W, l);
        k_wqk<<<(RR * FD + 255) / 256, 256>>>(W, aq, ak, l);
        dim3 gg((NN + 127) / 128, RR);
        k_gemm_mma<<<gg, 256, GSMEM>>>(l);
        k_s<<<(NN * 32 + 255) / 256, 256>>>(x, l);
        k_logit<<<(EE + 255) / 256, 256>>>(ei, et);
        k_expden<<<(EE + 255) / 256, 256>>>(ei);
        k_agg<<<((size_t)EE * 32 + 255) / 256, 256>>>(ei, et);
        k_out<<<(NF + 255) / 256, 256>>>(bias, out, l);
    }
}